// round 3
// baseline (speedup 1.0000x reference)
#include <cuda_runtime.h>
#include <cstdint>

#define S_LEN   2048
#define HID     4096
#define I_DIM   8192
#define CD      10240
#define H_HEADS 128
#define P_DIM   64
#define G_GRP   8
#define N_STATE 128
#define KCONV   4
#define PROJ    18560   // I + CD + H = 8192 + 10240 + 128

// device scratch (no dynamic allocation allowed)
__device__ float g_proj  [(size_t)S_LEN * PROJ ];
__device__ float g_conv  [(size_t)S_LEN * CD   ];
__device__ float g_y     [(size_t)S_LEN * I_DIM];
__device__ float g_normed[(size_t)S_LEN * I_DIM];

__device__ __forceinline__ float to_tf32(float x) {
    uint32_t u; asm("cvt.rna.tf32.f32 %0, %1;" : "=r"(u) : "f"(x));
    return __uint_as_float(u);
}
__device__ __forceinline__ void mma_tf32(float* d, const uint32_t* a, const uint32_t* b) {
    asm volatile("mma.sync.aligned.m16n8k8.row.col.f32.tf32.tf32.f32 "
        "{%0,%1,%2,%3}, {%4,%5,%6,%7}, {%8,%9}, {%0,%1,%2,%3};\n"
        : "+f"(d[0]), "+f"(d[1]), "+f"(d[2]), "+f"(d[3])
        : "r"(a[0]), "r"(a[1]), "r"(a[2]), "r"(a[3]), "r"(b[0]), "r"(b[1]));
}
__device__ __forceinline__ float silu_f(float v) { return v / (1.0f + expf(-v)); }

// ---------------- GEMM (NT): C[M][Nn] = A[M][Kk] * B[Nn][Kk]^T ----------------
__global__ __launch_bounds__(256, 1)
void gemm_tf32_nt(const float* __restrict__ A, const float* __restrict__ B,
                  float* __restrict__ C, int M, int Nn, int Kk)
{
    __shared__ float As[128 * 17];
    __shared__ float Bs[128 * 17];
    const int tid = threadIdx.x, lane = tid & 31, wid = tid >> 5;
    const int gid = lane >> 2, tig = lane & 3;
    const int wm = (wid >> 2) * 64, wn = (wid & 3) * 32;
    const int m0 = blockIdx.y * 128, n0 = blockIdx.x * 128;
    const int lr = tid >> 2, lc = (tid & 3) << 2;

    float acc[4][4][4];
    #pragma unroll
    for (int i = 0; i < 4; i++)
        #pragma unroll
        for (int j = 0; j < 4; j++)
            #pragma unroll
            for (int r = 0; r < 4; r++) acc[i][j][r] = 0.f;

    const float4 z4 = make_float4(0.f,0.f,0.f,0.f);
    float4 ra0 = *reinterpret_cast<const float4*>(&A[(size_t)(m0+lr)*Kk + lc]);
    float4 ra1 = *reinterpret_cast<const float4*>(&A[(size_t)(m0+lr+64)*Kk + lc]);
    float4 rb0, rb1;
    { int r = n0 + lr;
      rb0 = (r    < Nn) ? *reinterpret_cast<const float4*>(&B[(size_t)r     *Kk + lc]) : z4;
      rb1 = (r+64 < Nn) ? *reinterpret_cast<const float4*>(&B[(size_t)(r+64)*Kk + lc]) : z4; }

    for (int k0 = 0; k0 < Kk; k0 += 16) {
        { float* p0 = &As[lr*17 + lc];
          p0[0]=to_tf32(ra0.x); p0[1]=to_tf32(ra0.y); p0[2]=to_tf32(ra0.z); p0[3]=to_tf32(ra0.w);
          float* p1 = &As[(lr+64)*17 + lc];
          p1[0]=to_tf32(ra1.x); p1[1]=to_tf32(ra1.y); p1[2]=to_tf32(ra1.z); p1[3]=to_tf32(ra1.w);
          float* q0 = &Bs[lr*17 + lc];
          q0[0]=to_tf32(rb0.x); q0[1]=to_tf32(rb0.y); q0[2]=to_tf32(rb0.z); q0[3]=to_tf32(rb0.w);
          float* q1 = &Bs[(lr+64)*17 + lc];
          q1[0]=to_tf32(rb1.x); q1[1]=to_tf32(rb1.y); q1[2]=to_tf32(rb1.z); q1[3]=to_tf32(rb1.w); }
        __syncthreads();

        if (k0 + 16 < Kk) {
            const int kn = k0 + 16;
            ra0 = *reinterpret_cast<const float4*>(&A[(size_t)(m0+lr)*Kk + kn + lc]);
            ra1 = *reinterpret_cast<const float4*>(&A[(size_t)(m0+lr+64)*Kk + kn + lc]);
            int r = n0 + lr;
            rb0 = (r    < Nn) ? *reinterpret_cast<const float4*>(&B[(size_t)r     *Kk + kn + lc]) : z4;
            rb1 = (r+64 < Nn) ? *reinterpret_cast<const float4*>(&B[(size_t)(r+64)*Kk + kn + lc]) : z4;
        }

        #pragma unroll
        for (int ks = 0; ks < 16; ks += 8) {
            uint32_t af[4][4];
            #pragma unroll
            for (int mt = 0; mt < 4; mt++) {
                int r = wm + mt*16 + gid;
                af[mt][0] = __float_as_uint(As[ r   *17 + ks + tig  ]);
                af[mt][1] = __float_as_uint(As[(r+8)*17 + ks + tig  ]);
                af[mt][2] = __float_as_uint(As[ r   *17 + ks + tig+4]);
                af[mt][3] = __float_as_uint(As[(r+8)*17 + ks + tig+4]);
            }
            uint32_t bf[4][2];
            #pragma unroll
            for (int nt = 0; nt < 4; nt++) {
                int cn = wn + nt*8 + gid;
                bf[nt][0] = __float_as_uint(Bs[cn*17 + ks + tig  ]);
                bf[nt][1] = __float_as_uint(Bs[cn*17 + ks + tig+4]);
            }
            #pragma unroll
            for (int mt = 0; mt < 4; mt++)
                #pragma unroll
                for (int nt = 0; nt < 4; nt++)
                    mma_tf32(acc[mt][nt], af[mt], bf[nt]);
        }
        __syncthreads();
    }

    #pragma unroll
    for (int mt = 0; mt < 4; mt++) {
        int row = m0 + wm + mt*16 + gid;
        #pragma unroll
        for (int nt = 0; nt < 4; nt++) {
            int col = n0 + wn + nt*8 + 2*tig;
            if (col < Nn) {
                *reinterpret_cast<float2*>(&C[(size_t)row    *Nn + col]) = make_float2(acc[mt][nt][0], acc[mt][nt][1]);
                *reinterpret_cast<float2*>(&C[(size_t)(row+8)*Nn + col]) = make_float2(acc[mt][nt][2], acc[mt][nt][3]);
            }
        }
    }
}

// ---------------- conv1d K=4 + SiLU ----------------
__global__ __launch_bounds__(256)
void conv_kernel(const float* __restrict__ proj, const float* __restrict__ cstate,
                 const float* __restrict__ cw, const float* __restrict__ cb,
                 float* __restrict__ convout)
{
    const int c  = blockIdx.x * 256 + threadIdx.x;
    const int s0 = blockIdx.y * 128;
    const float w0 = cw[c*4+0], w1 = cw[c*4+1], w2 = cw[c*4+2], w3 = cw[c*4+3];
    const float bb = cb[c];
    auto xr = [&](int r) -> float {
        return (r < 0) ? cstate[c*4 + r + 4] : proj[(size_t)r*PROJ + I_DIM + c];
    };
    float x0 = xr(s0-3), x1 = xr(s0-2), x2 = xr(s0-1);
    #pragma unroll 4
    for (int s = s0; s < s0 + 128; s++) {
        float x3 = xr(s);
        float a  = bb + x0*w0 + x1*w1 + x2*w2 + x3*w3;
        convout[(size_t)s*CD + c] = silu_f(a);
        x0 = x1; x1 = x2; x2 = x3;
    }
}

__global__ void cstate_out_kernel(const float* __restrict__ proj, float* __restrict__ outc)
{
    int i = blockIdx.x * 256 + threadIdx.x;
    if (i < CD * KCONV) {
        int c = i >> 2, k = i & 3;
        outc[i] = proj[(size_t)(S_LEN - KCONV + k)*PROJ + I_DIM + c];
    }
}

// ---------------- sequential SSM scan: 1 block/head ----------------
__global__ __launch_bounds__(256, 1)
void scan_kernel(const float* __restrict__ proj, const float* __restrict__ conv,
                 const float* __restrict__ state_in,
                 const float* __restrict__ A_log, const float* __restrict__ Dv,
                 const float* __restrict__ dt_bias,
                 float* __restrict__ y_out, float* __restrict__ state_out)
{
    const int h = blockIdx.x, tid = threadIdx.x;
    const int p = tid >> 2, q = tid & 3;
    const int g = h >> 4;

    __shared__ __align__(16) float xs [3][64];
    __shared__ __align__(16) float Bsh[3][4*36];
    __shared__ __align__(16) float Csh[3][4*36];
    __shared__ float dts[3];

    const float Ah  = -expf(A_log[h]);
    const float Dh  = Dv[h];
    const float dtb = dt_bias[h];

    float st[32];
    { const float4* sp = reinterpret_cast<const float4*>(&state_in[((size_t)(h*64+p))*128 + q*32]);
      #pragma unroll
      for (int j = 0; j < 8; j++) {
          float4 v = sp[j];
          st[4*j+0]=v.x; st[4*j+1]=v.y; st[4*j+2]=v.z; st[4*j+3]=v.w;
      } }

    float rx = 0.f, rdt = 0.f;
    float4 rB = make_float4(0,0,0,0), rC = rB;

    auto issue_load = [&](int s) {
        const float* row = conv + (size_t)s * CD;
        if (tid < 64)        rx = row[h*64 + tid];
        else if (tid < 96)   rB = reinterpret_cast<const float4*>(row + I_DIM + g*128)[tid-64];
        else if (tid < 128)  rC = reinterpret_cast<const float4*>(row + I_DIM + G_GRP*N_STATE + g*128)[tid-96];
        else if (tid == 128) rdt = proj[(size_t)s*PROJ + I_DIM + CD + h];
    };
    auto store_smem = [&](int buf) {
        if (tid < 64)        xs[buf][tid] = rx;
        else if (tid < 96)  { int j = tid-64, qq = j>>3, jj = j&7;
                              *reinterpret_cast<float4*>(&Bsh[buf][qq*36 + jj*4]) = rB; }
        else if (tid < 128) { int j = tid-96, qq = j>>3, jj = j&7;
                              *reinterpret_cast<float4*>(&Csh[buf][qq*36 + jj*4]) = rC; }
        else if (tid == 128) dts[buf] = rdt;
    };

    issue_load(0);
    for (int s = 0; s < S_LEN; s++) {
        const int buf = s % 3;
        store_smem(buf);
        __syncthreads();
        if (s + 1 < S_LEN) issue_load(s + 1);

        const float dtr = dts[buf] + dtb;
        const float dt  = (dtr > 20.f) ? dtr : log1pf(expf(dtr));
        const float dA  = expf(dt * Ah);
        const float xv  = xs[buf][p];
        const float dx  = dt * xv;

        float accv = 0.f;
        const float4* bp = reinterpret_cast<const float4*>(&Bsh[buf][q*36]);
        const float4* cp = reinterpret_cast<const float4*>(&Csh[buf][q*36]);
        #pragma unroll
        for (int jj = 0; jj < 8; jj++) {
            float4 b4 = bp[jj], c4 = cp[jj];
            st[4*jj+0] = st[4*jj+0]*dA + dx*b4.x; accv += st[4*jj+0]*c4.x;
            st[4*jj+1] = st[4*jj+1]*dA + dx*b4.y; accv += st[4*jj+1]*c4.y;
            st[4*jj+2] = st[4*jj+2]*dA + dx*b4.z; accv += st[4*jj+2]*c4.z;
            st[4*jj+3] = st[4*jj+3]*dA + dx*b4.w; accv += st[4*jj+3]*c4.w;
        }
        accv += __shfl_xor_sync(0xffffffffu, accv, 1);
        accv += __shfl_xor_sync(0xffffffffu, accv, 2);
        if (q == 0) y_out[(size_t)s*I_DIM + h*64 + p] = accv + Dh*xv;
    }

    { float4* spo = reinterpret_cast<float4*>(&state_out[((size_t)(h*64+p))*128 + q*32]);
      #pragma unroll
      for (int j = 0; j < 8; j++)
          spo[j] = make_float4(st[4*j], st[4*j+1], st[4*j+2], st[4*j+3]); }
}

// ---------------- gate * silu + grouped RMSNorm ----------------
__global__ __launch_bounds__(256)
void gatenorm_kernel(const float* __restrict__ y, const float* __restrict__ proj,
                     const float* __restrict__ nw, float* __restrict__ outn)
{
    const int b = blockIdx.x, s = b >> 3, g = b & 7;
    const int tid = threadIdx.x, lane = tid & 31, wid = tid >> 5;

    float4 yv = *reinterpret_cast<const float4*>(&y   [(size_t)s*I_DIM + g*1024 + tid*4]);
    float4 gv = *reinterpret_cast<const float4*>(&proj[(size_t)s*PROJ  + g*1024 + tid*4]);
    float4 t;
    t.x = yv.x * silu_f(gv.x); t.y = yv.y * silu_f(gv.y);
    t.z = yv.z * silu_f(gv.z); t.w = yv.w * silu_f(gv.w);

    float ss = t.x*t.x + t.y*t.y + t.z*t.z + t.w*t.w;
    #pragma unroll
    for (int o = 16; o; o >>= 1) ss += __shfl_xor_sync(0xffffffffu, ss, o);

    __shared__ float red[8];
    __shared__ float sscale;
    if (lane == 0) red[wid] = ss;
    __syncthreads();
    if (tid == 0) {
        float tot = 0.f;
        #pragma unroll
        for (int i = 0; i < 8; i++) tot += red[i];
        sscale = rsqrtf(tot * (1.0f/1024.0f) + 1e-5f);
    }
    __syncthreads();
    const float sc = sscale;

    float4 wv = *reinterpret_cast<const float4*>(&nw[g*1024 + tid*4]);
    float4 o;
    o.x = t.x*sc*wv.x; o.y = t.y*sc*wv.y; o.z = t.z*sc*wv.z; o.w = t.w*sc*wv.w;
    *reinterpret_cast<float4*>(&outn[(size_t)s*I_DIM + g*1024 + tid*4]) = o;
}

// ---------------- launcher ----------------
extern "C" void kernel_launch(void* const* d_in, const int* in_sizes, int n_in,
                              void* d_out, int out_size)
{
    const float* hidden     = (const float*)d_in[0];
    const float* conv_state = (const float*)d_in[1];
    const float* ssm_state  = (const float*)d_in[2];
    const float* W_in       = (const float*)d_in[3];
    const float* W_out      = (const float*)d_in[4];
    const float* conv_w     = (const float*)d_in[5];
    const float* conv_b     = (const float*)d_in[6];
    const float* A_log      = (const float*)d_in[7];
    const float* Dv         = (const float*)d_in[8];
    const float* dt_bias    = (const float*)d_in[9];
    const float* norm_w     = (const float*)d_in[10];

    // outputs packed: [output (S*HID)] [conv_state_out (CD*K)] [ssm_state_out (H*P*N)]
    float* out_main   = (float*)d_out;
    float* out_cstate = out_main + (size_t)S_LEN * HID;
    float* out_sstate = out_cstate + (size_t)CD * KCONV;

    float* proj = nullptr, *conv = nullptr, *yb = nullptr, *normed = nullptr;
    cudaGetSymbolAddress((void**)&proj,   g_proj);
    cudaGetSymbolAddress((void**)&conv,   g_conv);
    cudaGetSymbolAddress((void**)&yb,     g_y);
    cudaGetSymbolAddress((void**)&normed, g_normed);

    // 1. projected = hidden @ W_in^T : M=2048, N=18560, K=4096
    {
        dim3 grid((PROJ + 127) / 128, S_LEN / 128);
        gemm_tf32_nt<<<grid, 256>>>(hidden, W_in, proj, S_LEN, PROJ, HID);
    }
    // 2. conv + silu ; conv_state_out
    {
        dim3 grid(CD / 256, S_LEN / 128);
        conv_kernel<<<grid, 256>>>(proj, conv_state, conv_w, conv_b, conv);
        cstate_out_kernel<<<(CD * KCONV + 255) / 256, 256>>>(proj, out_cstate);
    }
    // 3. scan
    scan_kernel<<<H_HEADS, 256>>>(proj, conv, ssm_state, A_log, Dv, dt_bias, yb, out_sstate);
    // 4. gate + norm
    gatenorm_kernel<<<S_LEN * G_GRP, 256>>>(yb, proj, norm_w, normed);
    // 5. output = normed @ W_out^T : M=2048, N=4096, K=8192
    {
        dim3 grid(HID / 128, S_LEN / 128);
        gemm_tf32_nt<<<grid, 256>>>(normed, W_out, out_main, S_LEN, HID, I_DIM);
    }
}

// round 4
// speedup vs baseline: 1.7500x; 1.7500x over previous
#include <cuda_runtime.h>
#include <cstdint>

#define S_LEN   2048
#define HID     4096
#define I_DIM   8192
#define CD      10240
#define H_HEADS 128
#define P_DIM   64
#define G_GRP   8
#define N_STATE 128
#define KCONV   4
#define PROJ    18560   // I + CD + H

// device scratch
__device__ float g_proj  [(size_t)S_LEN * PROJ ];
__device__ float g_conv  [(size_t)S_LEN * CD   ];
__device__ float g_y     [(size_t)S_LEN * I_DIM];
__device__ float g_normed[(size_t)S_LEN * I_DIM];

__device__ __forceinline__ float to_tf32(float x) {
    uint32_t u; asm("cvt.rna.tf32.f32 %0, %1;" : "=r"(u) : "f"(x));
    return __uint_as_float(u);
}
__device__ __forceinline__ uint32_t to_tf32_u(float x) {
    uint32_t u; asm("cvt.rna.tf32.f32 %0, %1;" : "=r"(u) : "f"(x));
    return u;
}
__device__ __forceinline__ void mma_tf32(float* d, const uint32_t* a, const uint32_t* b) {
    asm volatile("mma.sync.aligned.m16n8k8.row.col.f32.tf32.tf32.f32 "
        "{%0,%1,%2,%3}, {%4,%5,%6,%7}, {%8,%9}, {%0,%1,%2,%3};\n"
        : "+f"(d[0]), "+f"(d[1]), "+f"(d[2]), "+f"(d[3])
        : "r"(a[0]), "r"(a[1]), "r"(a[2]), "r"(a[3]), "r"(b[0]), "r"(b[1]));
}
__device__ __forceinline__ void cp_async16(void* smem_dst, const void* gmem_src) {
    uint32_t s = (uint32_t)__cvta_generic_to_shared(smem_dst);
    asm volatile("cp.async.cg.shared.global [%0], [%1], 16;" :: "r"(s), "l"(gmem_src) : "memory");
}
__device__ __forceinline__ float silu_f(float v) { return v / (1.0f + expf(-v)); }

// ---------------- GEMM (NT): C[M][Nn] = A[M][Kk] * B[Nn][Kk]^T ----------------
// Requirements: M,Nn multiples of 128; Kk multiple of 16 (true for all calls).
#define GSTG 3
#define KT   16
#define RS   20           // smem row stride in floats (80B: 16B-aligned, conflict-free)
#define TILEF (128 * RS)  // floats per tile buffer

__global__ __launch_bounds__(256, 2)
void gemm_tf32_nt(const float* __restrict__ A, const float* __restrict__ B,
                  float* __restrict__ C, int M, int Nn, int Kk)
{
    extern __shared__ float sm_[];
    float* Asm = sm_;                 // [GSTG][TILEF]
    float* Bsm = sm_ + GSTG * TILEF;  // [GSTG][TILEF]

    const int tid = threadIdx.x, lane = tid & 31, wid = tid >> 5;
    const int gid = lane >> 2, tig = lane & 3;
    const int wm = (wid >> 2) * 64, wn = (wid & 3) * 32;
    const int m0 = blockIdx.y * 128, n0 = blockIdx.x * 128;
    const int lr = tid >> 2, lc4 = (tid & 3) << 2;

    float acc[4][4][4];
    #pragma unroll
    for (int i = 0; i < 4; i++)
        #pragma unroll
        for (int j = 0; j < 4; j++)
            #pragma unroll
            for (int r = 0; r < 4; r++) acc[i][j][r] = 0.f;

    const float* Abase = &A[(size_t)(m0 + lr) * Kk + lc4];
    const float* Bbase = &B[(size_t)(n0 + lr) * Kk + lc4];
    const size_t rowskip = (size_t)64 * Kk;
    float* asd0 = 0; float* bsd0 = 0; // computed per stage below

    auto issue_stage = [&](int stg, int k0) {
        float* ad = Asm + stg * TILEF + lr * RS + lc4;
        float* bd = Bsm + stg * TILEF + lr * RS + lc4;
        cp_async16(ad,            Abase + k0);
        cp_async16(ad + 64 * RS,  Abase + k0 + rowskip);
        cp_async16(bd,            Bbase + k0);
        cp_async16(bd + 64 * RS,  Bbase + k0 + rowskip);
        asm volatile("cp.async.commit_group;" ::: "memory");
    };

    const int nk = Kk / KT;
    issue_stage(0, 0);
    issue_stage(1, KT);

    for (int i = 0; i < nk; i++) {
        if (i + 1 < nk) asm volatile("cp.async.wait_group 1;" ::: "memory");
        else            asm volatile("cp.async.wait_group 0;" ::: "memory");
        __syncthreads();
        if (i + 2 < nk) issue_stage((i + 2) % GSTG, (i + 2) * KT);

        const float* as = Asm + (i % GSTG) * TILEF;
        const float* bs = Bsm + (i % GSTG) * TILEF;

        #pragma unroll
        for (int ks = 0; ks < KT; ks += 8) {
            uint32_t af[4][4];
            #pragma unroll
            for (int mt = 0; mt < 4; mt++) {
                int r = wm + mt * 16 + gid;
                af[mt][0] = to_tf32_u(as[ r      * RS + ks + tig    ]);
                af[mt][1] = to_tf32_u(as[(r + 8) * RS + ks + tig    ]);
                af[mt][2] = to_tf32_u(as[ r      * RS + ks + tig + 4]);
                af[mt][3] = to_tf32_u(as[(r + 8) * RS + ks + tig + 4]);
            }
            uint32_t bf[4][2];
            #pragma unroll
            for (int nt = 0; nt < 4; nt++) {
                int cn = wn + nt * 8 + gid;
                bf[nt][0] = to_tf32_u(bs[cn * RS + ks + tig    ]);
                bf[nt][1] = to_tf32_u(bs[cn * RS + ks + tig + 4]);
            }
            #pragma unroll
            for (int mt = 0; mt < 4; mt++)
                #pragma unroll
                for (int nt = 0; nt < 4; nt++)
                    mma_tf32(acc[mt][nt], af[mt], bf[nt]);
        }
        // single barrier per iter: next iter's sync protects buffer reuse
        __syncthreads();
    }

    #pragma unroll
    for (int mt = 0; mt < 4; mt++) {
        int row = m0 + wm + mt * 16 + gid;
        #pragma unroll
        for (int nt = 0; nt < 4; nt++) {
            int col = n0 + wn + nt * 8 + 2 * tig;
            *reinterpret_cast<float2*>(&C[(size_t)row       * Nn + col]) = make_float2(acc[mt][nt][0], acc[mt][nt][1]);
            *reinterpret_cast<float2*>(&C[(size_t)(row + 8) * Nn + col]) = make_float2(acc[mt][nt][2], acc[mt][nt][3]);
        }
    }
}
#define GEMM_SMEM (GSTG * TILEF * 2 * (int)sizeof(float))   // 61440 B

// ---------------- conv1d K=4 + SiLU ----------------
__global__ __launch_bounds__(256)
void conv_kernel(const float* __restrict__ proj, const float* __restrict__ cstate,
                 const float* __restrict__ cw, const float* __restrict__ cb,
                 float* __restrict__ convout)
{
    const int c  = blockIdx.x * 256 + threadIdx.x;
    const int s0 = blockIdx.y * 128;
    const float w0 = cw[c*4+0], w1 = cw[c*4+1], w2 = cw[c*4+2], w3 = cw[c*4+3];
    const float bb = cb[c];
    auto xr = [&](int r) -> float {
        return (r < 0) ? cstate[c*4 + r + 4] : proj[(size_t)r*PROJ + I_DIM + c];
    };
    float x0 = xr(s0-3), x1 = xr(s0-2), x2 = xr(s0-1);
    #pragma unroll 4
    for (int s = s0; s < s0 + 128; s++) {
        float x3 = xr(s);
        float a  = bb + x0*w0 + x1*w1 + x2*w2 + x3*w3;
        convout[(size_t)s*CD + c] = silu_f(a);
        x0 = x1; x1 = x2; x2 = x3;
    }
}

__global__ void cstate_out_kernel(const float* __restrict__ proj, float* __restrict__ outc)
{
    int i = blockIdx.x * 256 + threadIdx.x;
    if (i < CD * KCONV) {
        int c = i >> 2, k = i & 3;
        outc[i] = proj[(size_t)(S_LEN - KCONV + k)*PROJ + I_DIM + c];
    }
}

// ---------------- sequential SSM scan: 1 block/head ----------------
__global__ __launch_bounds__(256, 1)
void scan_kernel(const float* __restrict__ proj, const float* __restrict__ conv,
                 const float* __restrict__ state_in,
                 const float* __restrict__ A_log, const float* __restrict__ Dv,
                 const float* __restrict__ dt_bias,
                 float* __restrict__ y_out, float* __restrict__ state_out)
{
    const int h = blockIdx.x, tid = threadIdx.x;
    const int p = tid >> 2, q = tid & 3;
    const int g = h >> 4;

    __shared__ __align__(16) float xs [3][64];
    __shared__ __align__(16) float Bsh[3][4*36];
    __shared__ __align__(16) float Csh[3][4*36];
    __shared__ float dts[3];

    const float Ah  = -expf(A_log[h]);
    const float Dh  = Dv[h];
    const float dtb = dt_bias[h];

    float st[32];
    { const float4* sp = reinterpret_cast<const float4*>(&state_in[((size_t)(h*64+p))*128 + q*32]);
      #pragma unroll
      for (int j = 0; j < 8; j++) {
          float4 v = sp[j];
          st[4*j+0]=v.x; st[4*j+1]=v.y; st[4*j+2]=v.z; st[4*j+3]=v.w;
      } }

    float rx = 0.f, rdt = 0.f;
    float4 rB = make_float4(0,0,0,0), rC = rB;

    auto issue_load = [&](int s) {
        const float* row = conv + (size_t)s * CD;
        if (tid < 64)        rx = row[h*64 + tid];
        else if (tid < 96)   rB = reinterpret_cast<const float4*>(row + I_DIM + g*128)[tid-64];
        else if (tid < 128)  rC = reinterpret_cast<const float4*>(row + I_DIM + G_GRP*N_STATE + g*128)[tid-96];
        else if (tid == 128) rdt = proj[(size_t)s*PROJ + I_DIM + CD + h];
    };
    auto store_smem = [&](int buf) {
        if (tid < 64)        xs[buf][tid] = rx;
        else if (tid < 96)  { int j = tid-64, qq = j>>3, jj = j&7;
                              *reinterpret_cast<float4*>(&Bsh[buf][qq*36 + jj*4]) = rB; }
        else if (tid < 128) { int j = tid-96, qq = j>>3, jj = j&7;
                              *reinterpret_cast<float4*>(&Csh[buf][qq*36 + jj*4]) = rC; }
        else if (tid == 128) dts[buf] = rdt;
    };

    issue_load(0);
    for (int s = 0; s < S_LEN; s++) {
        const int buf = s % 3;
        store_smem(buf);
        __syncthreads();
        if (s + 1 < S_LEN) issue_load(s + 1);

        const float dtr = dts[buf] + dtb;
        const float dt  = (dtr > 20.f) ? dtr : log1pf(expf(dtr));
        const float dA  = expf(dt * Ah);
        const float xv  = xs[buf][p];
        const float dx  = dt * xv;

        float accv = 0.f;
        const float4* bp = reinterpret_cast<const float4*>(&Bsh[buf][q*36]);
        const float4* cp = reinterpret_cast<const float4*>(&Csh[buf][q*36]);
        #pragma unroll
        for (int jj = 0; jj < 8; jj++) {
            float4 b4 = bp[jj], c4 = cp[jj];
            st[4*jj+0] = st[4*jj+0]*dA + dx*b4.x; accv += st[4*jj+0]*c4.x;
            st[4*jj+1] = st[4*jj+1]*dA + dx*b4.y; accv += st[4*jj+1]*c4.y;
            st[4*jj+2] = st[4*jj+2]*dA + dx*b4.z; accv += st[4*jj+2]*c4.z;
            st[4*jj+3] = st[4*jj+3]*dA + dx*b4.w; accv += st[4*jj+3]*c4.w;
        }
        accv += __shfl_xor_sync(0xffffffffu, accv, 1);
        accv += __shfl_xor_sync(0xffffffffu, accv, 2);
        if (q == 0) y_out[(size_t)s*I_DIM + h*64 + p] = accv + Dh*xv;
    }

    { float4* spo = reinterpret_cast<float4*>(&state_out[((size_t)(h*64+p))*128 + q*32]);
      #pragma unroll
      for (int j = 0; j < 8; j++)
          spo[j] = make_float4(st[4*j], st[4*j+1], st[4*j+2], st[4*j+3]); }
}

// ---------------- gate * silu + grouped RMSNorm ----------------
__global__ __launch_bounds__(256)
void gatenorm_kernel(const float* __restrict__ y, const float* __restrict__ proj,
                     const float* __restrict__ nw, float* __restrict__ outn)
{
    const int b = blockIdx.x, s = b >> 3, g = b & 7;
    const int tid = threadIdx.x, lane = tid & 31, wid = tid >> 5;

    float4 yv = *reinterpret_cast<const float4*>(&y   [(size_t)s*I_DIM + g*1024 + tid*4]);
    float4 gv = *reinterpret_cast<const float4*>(&proj[(size_t)s*PROJ  + g*1024 + tid*4]);
    float4 t;
    t.x = yv.x * silu_f(gv.x); t.y = yv.y * silu_f(gv.y);
    t.z = yv.z * silu_f(gv.z); t.w = yv.w * silu_f(gv.w);

    float ss = t.x*t.x + t.y*t.y + t.z*t.z + t.w*t.w;
    #pragma unroll
    for (int o = 16; o; o >>= 1) ss += __shfl_xor_sync(0xffffffffu, ss, o);

    __shared__ float red[8];
    __shared__ float sscale;
    if (lane == 0) red[wid] = ss;
    __syncthreads();
    if (tid == 0) {
        float tot = 0.f;
        #pragma unroll
        for (int i = 0; i < 8; i++) tot += red[i];
        sscale = rsqrtf(tot * (1.0f/1024.0f) + 1e-5f);
    }
    __syncthreads();
    const float sc = sscale;

    float4 wv = *reinterpret_cast<const float4*>(&nw[g*1024 + tid*4]);
    float4 o;
    o.x = t.x*sc*wv.x; o.y = t.y*sc*wv.y; o.z = t.z*sc*wv.z; o.w = t.w*sc*wv.w;
    *reinterpret_cast<float4*>(&outn[(size_t)s*I_DIM + g*1024 + tid*4]) = o;
}

// ---------------- launcher ----------------
extern "C" void kernel_launch(void* const* d_in, const int* in_sizes, int n_in,
                              void* d_out, int out_size)
{
    const float* hidden     = (const float*)d_in[0];
    const float* conv_state = (const float*)d_in[1];
    const float* ssm_state  = (const float*)d_in[2];
    const float* W_in       = (const float*)d_in[3];
    const float* W_out      = (const float*)d_in[4];
    const float* conv_w     = (const float*)d_in[5];
    const float* conv_b     = (const float*)d_in[6];
    const float* A_log      = (const float*)d_in[7];
    const float* Dv         = (const float*)d_in[8];
    const float* dt_bias    = (const float*)d_in[9];
    const float* norm_w     = (const float*)d_in[10];

    float* out_main   = (float*)d_out;
    float* out_cstate = out_main + (size_t)S_LEN * HID;
    float* out_sstate = out_cstate + (size_t)CD * KCONV;

    float* proj = nullptr, *conv = nullptr, *yb = nullptr, *normed = nullptr;
    cudaGetSymbolAddress((void**)&proj,   g_proj);
    cudaGetSymbolAddress((void**)&conv,   g_conv);
    cudaGetSymbolAddress((void**)&yb,     g_y);
    cudaGetSymbolAddress((void**)&normed, g_normed);

    cudaFuncSetAttribute(gemm_tf32_nt, cudaFuncAttributeMaxDynamicSharedMemorySize, GEMM_SMEM);

    // 1. projected = hidden @ W_in^T : M=2048, N=18560, K=4096
    {
        dim3 grid(PROJ / 128, S_LEN / 128);
        gemm_tf32_nt<<<grid, 256, GEMM_SMEM>>>(hidden, W_in, proj, S_LEN, PROJ, HID);
    }
    // 2. conv + silu ; conv_state_out
    {
        dim3 grid(CD / 256, S_LEN / 128);
        conv_kernel<<<grid, 256>>>(proj, conv_state, conv_w, conv_b, conv);
        cstate_out_kernel<<<(CD * KCONV + 255) / 256, 256>>>(proj, out_cstate);
    }
    // 3. scan
    scan_kernel<<<H_HEADS, 256>>>(proj, conv, ssm_state, A_log, Dv, dt_bias, yb, out_sstate);
    // 4. gate + norm
    gatenorm_kernel<<<S_LEN * G_GRP, 256>>>(yb, proj, norm_w, normed);
    // 5. output = normed @ W_out^T : M=2048, N=4096, K=8192
    {
        dim3 grid(HID / 128, S_LEN / 128);
        gemm_tf32_nt<<<grid, 256, GEMM_SMEM>>>(normed, W_out, out_main, S_LEN, HID, I_DIM);
    }
}